// round 16
// baseline (speedup 1.0000x reference)
#include <cuda_runtime.h>
#include <cstdint>

// Problem constants (fixed by dataset: B=16, H=1024, W=2048, G=8, C=19)
#define NB      524288
#define NC      19
#define WID     2048
#define HEI     1024
#define GS      8
#define BLOCKS_PER_TILE 128                    // half a block-row
#define NTILES  (NB/BLOCKS_PER_TILE)           // 4096
#define TGT_ROW_BYTES 4096                     // 1024 px * 4B per strip row
#define TGT_BYTES (8*TGT_ROW_BYTES)            // 32768
#define PRED_BYTES (BLOCKS_PER_TILE*NC*4)      // 9728 (16B multiple)
#define STAGE_TX  (TGT_BYTES + PRED_BYTES)     // 42496
#define NSTAGE  2
#define NTHREADS 256
#define GRID    304                            // 2 CTAs per SM
#define V_PER_TILE (BLOCKS_PER_TILE*NC/4)      // 608 float4

// Allocation-free scratch (__device__ globals per harness rules)
__device__ double       g_partials[NTILES];    // per-TILE partials (deterministic)
__device__ unsigned int g_tile  = NSTAGE * GRID;  // steal counter (self-reset)
__device__ unsigned int g_count = 0;              // completion counter (self-reset)

// Numerically stable softplus: max(x,0) + log(1 + exp(-|x|))
__device__ __forceinline__ float softplus_f(float x)
{
    float e = __expf(-fabsf(x));
    return fmaxf(x, 0.0f) + __logf(1.0f + e);
}

__device__ __forceinline__ void mbar_init(uint32_t mbar, unsigned count)
{
    asm volatile("mbarrier.init.shared.b64 [%0], %1;" :: "r"(mbar), "r"(count) : "memory");
}

__device__ __forceinline__ void mbar_wait(uint32_t mbar, unsigned phase)
{
    asm volatile(
        "{\n\t.reg .pred P;\n\t"
        "WAIT_%=:\n\t"
        "mbarrier.try_wait.parity.acquire.cta.shared::cta.b64 P, [%0], %1, 0x989680;\n\t"
        "@P bra DONE_%=;\n\t"
        "bra WAIT_%=;\n\t"
        "DONE_%=:\n\t}"
        :: "r"(mbar), "r"(phase) : "memory");
}

__device__ __forceinline__ void bulk_cp(uint32_t dst_smem, const void* src,
                                        unsigned bytes, uint32_t mbar)
{
    asm volatile(
        "cp.async.bulk.shared::cluster.global.mbarrier::complete_tx::bytes "
        "[%0], [%1], %2, [%3];"
        :: "r"(dst_smem), "l"(src), "r"(bytes), "r"(mbar) : "memory");
}

__device__ __forceinline__ const char* tile_tgt_src(const int* tgt, unsigned tile)
{
    unsigned half = tile & 1u;
    unsigned bh   = (tile >> 1) & 127u;
    unsigned bimg = tile >> 8;
    return (const char*)(tgt
        + ((size_t)(bimg * HEI + bh * GS)) * WID + (size_t)half * 1024u);
}

// Arm expect_tx (full stage) + issue the 8 target-row copies.
__device__ __forceinline__ void issue_targets(const int* tgt, unsigned tile,
                                              uint32_t stage, uint32_t mbar)
{
    asm volatile("mbarrier.arrive.expect_tx.shared.b64 _, [%0], %1;"
                 :: "r"(mbar), "r"((unsigned)STAGE_TX) : "memory");
    const char* tsrc = tile_tgt_src(tgt, tile);
#pragma unroll
    for (int r = 0; r < 8; r++)
        bulk_cp(stage + r * TGT_ROW_BYTES, tsrc + (size_t)r * WID * 4,
                TGT_ROW_BYTES, mbar);
}

// ---------------------------------------------------------------------------
// R12 pipeline (304 CTAs x 256 thr, 2 stages x 42.5KB) + tile work-stealing.
// Steal atomic issued at END of previous iteration (hidden under mbar_wait).
// Per-tile partials keep the reduction deterministic under stealing.
// Split refill: targets re-issue at the mask barrier, preds after consume.
// ---------------------------------------------------------------------------
__global__ void __launch_bounds__(NTHREADS)
fused_kernel(const int*   __restrict__ tgt,
             const float* __restrict__ preds,
             float*       __restrict__ out)
{
    extern __shared__ char stage_mem[];                 // NSTAGE * STAGE_TX
    __shared__ unsigned long long mbar_store[NSTAGE];
    __shared__ unsigned int sm_mask[BLOCKS_PER_TILE + 1];
    __shared__ unsigned int sm_next;
    __shared__ float  ws[8];
    __shared__ double sh[NTHREADS];

    const unsigned tid  = threadIdx.x;
    const unsigned lane = tid & 31u;
    const unsigned wix  = tid >> 5;
    const unsigned cta  = blockIdx.x;

    const uint32_t stage0 = (uint32_t)__cvta_generic_to_shared(stage_mem);
    const uint32_t mbb    = (uint32_t)__cvta_generic_to_shared(&mbar_store[0]);

    if (tid == 0) {
        mbar_init(mbb, 1);
        mbar_init(mbb + 8u, 1);
        asm volatile("fence.proxy.async.shared::cta;" ::: "memory");
        // Prologue: fill both stages with static tiles cta, cta+GRID
#pragma unroll
        for (unsigned k = 0; k < NSTAGE; k++) {
            uint32_t stg = stage0 + k * STAGE_TX;
            uint32_t mb  = mbb + 8u * k;
            unsigned t0i = cta + k * GRID;
            issue_targets(tgt, t0i, stg, mb);
            bulk_cp(stg + TGT_BYTES,
                    (const char*)preds + (size_t)t0i * PRED_BYTES,
                    PRED_BYTES, mb);
        }
        sm_next = atomicAdd(&g_tile, 1u);   // steal for first refill
    }
    __syncthreads();

    unsigned mytile0 = cta, mytile1 = cta + GRID;
    unsigned ph0 = 0, ph1 = 0;

    for (unsigned n = 0;; n++) {
        const unsigned k   = n & 1u;
        const unsigned cur = k ? mytile1 : mytile0;
        if (cur >= NTILES) break;

        const uint32_t stg  = stage0 + k * STAGE_TX;
        const char*    stgp = stage_mem + (size_t)k * STAGE_TX;
        const uint32_t mb   = mbb + 8u * k;

        if (k) { mbar_wait(mb, ph1); ph1 ^= 1u; }
        else   { mbar_wait(mb, ph0); ph0 ^= 1u; }

        // ---- masks: thread pair (2p, 2p+1) covers block p's 16B halves ----
        {
            unsigned p = tid >> 1, h = tid & 1u;
            unsigned m = 0u;
#pragma unroll
            for (int r = 0; r < 8; r++) {
                int4 v = *(const int4*)(stgp + r * TGT_ROW_BYTES + p * 32u + h * 16u);
                m |= (1u << v.x) | (1u << v.y) | (1u << v.z) | (1u << v.w);
            }
            m |= __shfl_xor_sync(0xffffffffu, m, 1);
            if (h == 0u) sm_mask[p] = m;
            if (tid == 0u) sm_mask[BLOCKS_PER_TILE] = 0u;
        }
        __syncthreads();          // masks + sm_next visible; targets region dead

        const unsigned nt = sm_next;         // refill tile for this stage
        if (k) mytile1 = nt; else mytile0 = nt;

        // refill targets early: overlaps the preds compute below
        if (tid == 0u && nt < NTILES)
            issue_targets(tgt, nt, stg, mb);

        // ---- preds: 608 float4 from smem, softplus + correction ----
        const float4* pvs = (const float4*)(stgp + TGT_BYTES);
        float ts = 0.0f;
#pragma unroll
        for (int it = 0; it < 3; it++) {
            unsigned j = tid + (unsigned)it * NTHREADS;
            if (it == 2 && tid >= (V_PER_TILE - 512)) break;   // tail: tid < 96
            unsigned e0 = j * 4u;
            unsigned q  = e0 / 19u;                 // 0..127 (magic div)
            unsigned c0 = e0 - q * 19u;             // 0..18
            unsigned mm = (sm_mask[q] | (sm_mask[q + 1] << 19)) >> c0;
            float4 x = pvs[j];
            ts += softplus_f(x.x) + softplus_f(x.y)
                + softplus_f(x.z) + softplus_f(x.w);
            if (mm & 1u) ts -= x.x;
            if (mm & 2u) ts -= x.y;
            if (mm & 4u) ts -= x.z;
            if (mm & 8u) ts -= x.w;
        }

        // ---- per-tile fixed-tree reduction -> g_partials[cur] ----
#pragma unroll
        for (int o = 16; o > 0; o >>= 1)
            ts += __shfl_xor_sync(0xffffffffu, ts, o);
        if (lane == 0u) ws[wix] = ts;
        __syncthreads();
        if (tid < 32u) {
            float v = (tid < 8u) ? ws[tid] : 0.0f;
#pragma unroll
            for (int o = 4; o > 0; o >>= 1)
                v += __shfl_xor_sync(0xffffffffu, v, o);
            if (tid == 0u)
                g_partials[cur] = (double)v;
        }
        __syncthreads();          // preds reads done; ws consumed

        // complete stage refill + steal for NEXT iteration (latency hidden
        // under the next mbar_wait)
        if (tid == 0u) {
            if (nt < NTILES)
                bulk_cp(stg + TGT_BYTES,
                        (const char*)preds + (size_t)nt * PRED_BYTES,
                        PRED_BYTES, mb);
            sm_next = atomicAdd(&g_tile, 1u);
        }
    }

    // ---- Completion: last CTA reduces all tile partials (fixed order) ----
    if (tid == 0) {
        __threadfence();
        unsigned done = atomicAdd(&g_count, 1u);
        ws[0] = (done == (unsigned)(GRID - 1)) ? 1.0f : 0.0f;
    }
    __syncthreads();
    if (ws[0] == 0.0f) return;

    double d = 0.0;
    for (unsigned i = tid; i < (unsigned)NTILES; i += NTHREADS)
        d += g_partials[i];
    sh[tid] = d;
    __syncthreads();
#pragma unroll
    for (int o = NTHREADS / 2; o > 0; o >>= 1) {
        if (tid < (unsigned)o) sh[tid] += sh[tid + o];
        __syncthreads();
    }
    if (tid == 0) {
        out[0] = (float)(sh[0] / ((double)NB * (double)NC));
        g_tile  = NSTAGE * GRID;    // reset for next graph replay
        g_count = 0;
    }
}

// ---------------------------------------------------------------------------
extern "C" void kernel_launch(void* const* d_in, const int* in_sizes, int n_in,
                              void* d_out, int out_size)
{
    const float* preds = (const float*)d_in[0];
    const int*   tgt   = (const int*)d_in[1];
    // d_in[2] = grid_size (always 8 for this problem's shapes)

    static int smem_set = 0;
    if (!smem_set) {
        cudaFuncSetAttribute(fused_kernel,
                             cudaFuncAttributeMaxDynamicSharedMemorySize,
                             NSTAGE * STAGE_TX);
        smem_set = 1;
    }
    fused_kernel<<<GRID, NTHREADS, NSTAGE * STAGE_TX>>>(tgt, preds, (float*)d_out);
}

// round 17
// speedup vs baseline: 1.1308x; 1.1308x over previous
#include <cuda_runtime.h>
#include <cstdint>

// Problem constants (fixed by dataset: B=16, H=1024, W=2048, G=8, C=19)
#define NB      524288
#define NC      19
#define WID     2048
#define HEI     1024
#define GS      8
#define BLOCKS_PER_TILE 128                    // half a block-row
#define NTILES  (NB/BLOCKS_PER_TILE)           // 4096
#define TGT_ROW_BYTES 4096                     // 1024 px * 4B per strip row
#define TGT_BYTES (8*TGT_ROW_BYTES)            // 32768
#define PRED_BYTES (BLOCKS_PER_TILE*NC*4)      // 9728 (16B multiple)
#define STAGE_BYTES (TGT_BYTES + PRED_BYTES)   // 42496
#define NSTAGE  2
#define GRID    304                            // 2 CTAs per SM (152 SMs)
#define V_PER_TILE (BLOCKS_PER_TILE*NC/4)      // 608 float4

// Allocation-free scratch (__device__ globals per harness rules)
__device__ double       g_partials[GRID];
__device__ unsigned int g_count = 0;           // self-resetting completion counter

// Numerically stable softplus: max(x,0) + log(1 + exp(-|x|))
__device__ __forceinline__ float softplus_f(float x)
{
    float e = __expf(-fabsf(x));
    return fmaxf(x, 0.0f) + __logf(1.0f + e);
}

__device__ __forceinline__ void mbar_init(uint32_t mbar, unsigned count)
{
    asm volatile("mbarrier.init.shared.b64 [%0], %1;" :: "r"(mbar), "r"(count) : "memory");
}

__device__ __forceinline__ void mbar_wait(uint32_t mbar, unsigned phase)
{
    asm volatile(
        "{\n\t.reg .pred P;\n\t"
        "WAIT_%=:\n\t"
        "mbarrier.try_wait.parity.acquire.cta.shared::cta.b64 P, [%0], %1, 0x989680;\n\t"
        "@P bra DONE_%=;\n\t"
        "bra WAIT_%=;\n\t"
        "DONE_%=:\n\t}"
        :: "r"(mbar), "r"(phase) : "memory");
}

__device__ __forceinline__ void bulk_cp(uint32_t dst_smem, const void* src,
                                        unsigned bytes, uint32_t mbar)
{
    asm volatile(
        "cp.async.bulk.shared::cluster.global.mbarrier::complete_tx::bytes "
        "[%0], [%1], %2, [%3];"
        :: "r"(dst_smem), "l"(src), "r"(bytes), "r"(mbar) : "memory");
}

__device__ __forceinline__ const char* tile_tgt_src(const int* tgt, unsigned tile)
{
    unsigned half = tile & 1u;
    unsigned bh   = (tile >> 1) & 127u;
    unsigned bimg = tile >> 8;
    return (const char*)(tgt
        + ((size_t)(bimg * HEI + bh * GS)) * WID + (size_t)half * 1024u);
}

// Arm expect_tx for the FULL stage and issue the 8 target-row copies.
__device__ __forceinline__ void issue_targets(const int* tgt, unsigned tile,
                                              uint32_t stage, uint32_t mbar)
{
    asm volatile("mbarrier.arrive.expect_tx.shared.b64 _, [%0], %1;"
                 :: "r"(mbar), "r"((unsigned)STAGE_BYTES) : "memory");
    const char* tsrc = tile_tgt_src(tgt, tile);
#pragma unroll
    for (int r = 0; r < 8; r++)
        bulk_cp(stage + r * TGT_ROW_BYTES, tsrc + (size_t)r * WID * 4,
                TGT_ROW_BYTES, mbar);
}

// ---------------------------------------------------------------------------
// R12 pipeline (304 CTAs x 256 thr, 2 stages x 42.5KB, static tiles) with
// SPLIT REFILL: targets re-issue right after the mask barrier (region dead),
// preds copy after the consume barrier. Strictly earlier request issue than
// R12, zero added barriers or per-tile work.
// ---------------------------------------------------------------------------
__global__ void __launch_bounds__(256)
fused_kernel(const int*   __restrict__ tgt,
             const float* __restrict__ preds,
             float*       __restrict__ out)
{
    extern __shared__ char stage_mem[];                 // NSTAGE * STAGE_BYTES
    __shared__ unsigned long long mbar_store[NSTAGE];
    __shared__ unsigned int sm_mask[BLOCKS_PER_TILE + 1];
    __shared__ float  ws[8];
    __shared__ double sh[256];

    const unsigned tid  = threadIdx.x;
    const unsigned lane = tid & 31u;
    const unsigned wix  = tid >> 5;
    const unsigned cta  = blockIdx.x;

    const uint32_t stage0 = (uint32_t)__cvta_generic_to_shared(stage_mem);
    const uint32_t mb0    = (uint32_t)__cvta_generic_to_shared(&mbar_store[0]);
    const uint32_t mb1    = (uint32_t)__cvta_generic_to_shared(&mbar_store[1]);

    if (tid == 0) {
        mbar_init(mb0, 1);
        mbar_init(mb1, 1);
        asm volatile("fence.proxy.async.shared::cta;" ::: "memory");
        // Prologue: fill both stages (every CTA has >= 13 tiles)
        issue_targets(tgt, cta, stage0, mb0);
        bulk_cp(stage0 + TGT_BYTES,
                (const char*)preds + (size_t)cta * PRED_BYTES, PRED_BYTES, mb0);
        issue_targets(tgt, cta + GRID, stage0 + STAGE_BYTES, mb1);
        bulk_cp(stage0 + STAGE_BYTES + TGT_BYTES,
                (const char*)preds + (size_t)(cta + GRID) * PRED_BYTES,
                PRED_BYTES, mb1);
    }
    __syncthreads();

    unsigned ph0 = 0, ph1 = 0;
    float s = 0.0f;
    unsigned n = 0;

    for (unsigned tile = cta; tile < NTILES; tile += GRID, n++) {
        const unsigned k = n & 1u;
        const uint32_t  stg  = stage0 + k * STAGE_BYTES;
        const char*     stgp = stage_mem + (size_t)k * STAGE_BYTES;
        const uint32_t  mb   = k ? mb1 : mb0;
        const unsigned  nt   = tile + NSTAGE * GRID;    // refill tile (if any)

        // wait for this stage's data
        if (k) { mbar_wait(mb, ph1); ph1 ^= 1u; }
        else   { mbar_wait(mb, ph0); ph0 ^= 1u; }

        // ---- masks: thread pair (2p, 2p+1) covers block p's 16B halves ----
        {
            unsigned p = tid >> 1, h = tid & 1u;
            unsigned m = 0u;
#pragma unroll
            for (int r = 0; r < 8; r++) {
                int4 v = *(const int4*)(stgp + r * TGT_ROW_BYTES + p * 32u + h * 16u);
                m |= (1u << v.x) | (1u << v.y) | (1u << v.z) | (1u << v.w);
            }
            m |= __shfl_xor_sync(0xffffffffu, m, 1);
            if (h == 0u) sm_mask[p] = m;
            if (tid == 0u) sm_mask[BLOCKS_PER_TILE] = 0u;
        }
        __syncthreads();                 // masks visible; targets region dead

        // split refill part 1: targets re-issue NOW, overlapping preds compute
        if (tid == 0u && nt < NTILES)
            issue_targets(tgt, nt, stg, mb);

        // ---- preds: 608 float4 from smem, softplus + correction ----
        const float4* pvs = (const float4*)(stgp + TGT_BYTES);
#pragma unroll
        for (int it = 0; it < 3; it++) {
            unsigned j = tid + (unsigned)it * 256u;
            if (it == 2 && tid >= (V_PER_TILE - 512)) break;   // tail: tid < 96
            unsigned e0 = j * 4u;
            unsigned q  = e0 / 19u;                 // 0..127 (magic div)
            unsigned c0 = e0 - q * 19u;             // 0..18
            unsigned mm = (sm_mask[q] | (sm_mask[q + 1] << 19)) >> c0;
            float4 x = pvs[j];
            s += softplus_f(x.x) + softplus_f(x.y)
               + softplus_f(x.z) + softplus_f(x.w);
            if (mm & 1u) s -= x.x;
            if (mm & 2u) s -= x.y;
            if (mm & 4u) s -= x.z;
            if (mm & 8u) s -= x.w;
        }
        __syncthreads();                 // all smem reads of this stage done

        // split refill part 2: preds copy completes the stage's expect_tx
        if (tid == 0u && nt < NTILES)
            bulk_cp(stg + TGT_BYTES,
                    (const char*)preds + (size_t)nt * PRED_BYTES,
                    PRED_BYTES, mb);
    }

    // ---- per-CTA fixed-tree reduction -> double partial ----
#pragma unroll
    for (int o = 16; o > 0; o >>= 1)
        s += __shfl_xor_sync(0xffffffffu, s, o);
    if (lane == 0u) ws[wix] = s;
    __syncthreads();
    if (tid < 32u) {
        float v = (tid < 8u) ? ws[tid] : 0.0f;
#pragma unroll
        for (int o = 4; o > 0; o >>= 1)
            v += __shfl_xor_sync(0xffffffffu, v, o);
        if (tid == 0u) {
            g_partials[cta] = (double)v;
            __threadfence();
            unsigned done = atomicAdd(&g_count, 1u);
            ws[0] = (done == (unsigned)(GRID - 1)) ? 1.0f : 0.0f;
        }
    }
    __syncthreads();
    if (ws[0] == 0.0f) return;

    // ---- Last CTA: deterministic final reduction over CTA partials ----
    double d = 0.0;
    for (unsigned i = tid; i < (unsigned)GRID; i += 256u)
        d += g_partials[i];
    sh[tid] = d;
    __syncthreads();
#pragma unroll
    for (int o = 128; o > 0; o >>= 1) {
        if (tid < (unsigned)o) sh[tid] += sh[tid + o];
        __syncthreads();
    }
    if (tid == 0) {
        out[0] = (float)(sh[0] / ((double)NB * (double)NC));
        g_count = 0;                     // reset for next graph replay
    }
}

// ---------------------------------------------------------------------------
extern "C" void kernel_launch(void* const* d_in, const int* in_sizes, int n_in,
                              void* d_out, int out_size)
{
    const float* preds = (const float*)d_in[0];
    const int*   tgt   = (const int*)d_in[1];
    // d_in[2] = grid_size (always 8 for this problem's shapes)

    static int smem_set = 0;
    if (!smem_set) {
        cudaFuncSetAttribute(fused_kernel,
                             cudaFuncAttributeMaxDynamicSharedMemorySize,
                             NSTAGE * STAGE_BYTES);
        smem_set = 1;
    }
    fused_kernel<<<GRID, 256, NSTAGE * STAGE_BYTES>>>(tgt, preds, (float*)d_out);
}